// round 1
// baseline (speedup 1.0000x reference)
#include <cuda_runtime.h>
#include <math.h>

// Dynamics_79843442033036 — fused analytic grad/Hessian-vector kernel.
// out_q = force_q - g_q * (g.force + v^T H v) / (1 + g.g)
// g via backprop; v^T H v via forward-over-forward (2nd directional derivative).

#define HID     128
#define DIMV    8
#define BATCHN  65536
#define TBS     64                 // samples per CTA tile
#define NTILES  (BATCHN / TBS)     // 1024
#define NTHREADS 512
#define GRID    152                // GB300: 152 SMs, persistent CTAs

#define W1P 129                    // padded pitch (conflict-free scalar reads)
#define XP  17
#define W0P 9

// shared memory layout (floats)
#define SM_W1   0
#define SM_H1   (SM_W1 + HID*W1P)        // 16512
#define SM_E1   (SM_H1 + HID*TBS)
#define SM_F1   (SM_E1 + HID*TBS)
#define SM_X    (SM_F1 + HID*TBS)        // [64][17]
#define SM_W0   (SM_X + TBS*XP)          // [128][9]
#define SM_B0   (SM_W0 + HID*W0P)
#define SM_B1   (SM_B0 + HID)
#define SM_W2   (SM_B1 + HID)
#define SM_K    (SM_W2 + HID)
#define SM_D    (SM_K + 64)
#define SM_G    (SM_D + 64)              // [8][64]
#define SM_HVV  (SM_G + 8*TBS)           // [64]
#define SM_TOTAL (SM_HVV + TBS)
#define SMEM_BYTES (SM_TOTAL * sizeof(float))

extern "C" __global__ void __launch_bounds__(NTHREADS, 1)
dyn_kernel(const float* __restrict__ X,  const float* __restrict__ Km,
           const float* __restrict__ Dm, const float* __restrict__ W0,
           const float* __restrict__ b0, const float* __restrict__ W1,
           const float* __restrict__ b1, const float* __restrict__ W2,
           float* __restrict__ out)
{
    extern __shared__ float sm[];
    float* W1s = sm + SM_W1;
    float* h1s = sm + SM_H1;
    float* e1s = sm + SM_E1;
    float* f1s = sm + SM_F1;
    float* Xs  = sm + SM_X;
    float* W0s = sm + SM_W0;
    float* b0s = sm + SM_B0;
    float* b1s = sm + SM_B1;
    float* w2s = sm + SM_W2;
    float* Ks  = sm + SM_K;
    float* Ds  = sm + SM_D;
    float* gbf = sm + SM_G;
    float* hvs = sm + SM_HVV;

    const int tid = threadIdx.x;

    // ---- one-time weight staging ----
    for (int idx = tid; idx < HID*HID; idx += NTHREADS) {
        int j = idx >> 7, i = idx & 127;
        W1s[j*W1P + i] = W1[idx];
    }
    for (int idx = tid; idx < HID*DIMV; idx += NTHREADS) {
        int i = idx >> 3, k = idx & 7;
        W0s[i*W0P + k] = W0[idx];
    }
    if (tid < HID) { b0s[tid] = b0[tid]; b1s[tid] = b1[tid]; w2s[tid] = W2[tid]; }
    if (tid < 64)  { Ks[tid] = Km[tid]; Ds[tid] = Dm[tid]; }
    __syncthreads();

    const int tx = tid & 15;     // sample-group (16 groups x 4 samples)
    const int jy = tid >> 4;     // hidden-group (32 groups x 4 rows)
    const int s0 = tx * 4;
    const int j0 = jy * 4;
    const int qf = tid & 7;      // final-phase mapping (coalesced store)
    const int sf = tid >> 3;

    for (int tile = blockIdx.x; tile < NTILES; tile += gridDim.x) {
        const int base = tile * TBS;

        // ---- stage X tile ----
        for (int idx = tid; idx < TBS*16; idx += NTHREADS) {
            int s = idx >> 4, k = idx & 15;
            Xs[s*XP + k] = X[base*16 + idx];
        }
        __syncthreads();

        // ---- phase 1: layer-1 forward + directional (h1, h1', h1'') ----
        #pragma unroll
        for (int ss = 0; ss < 4; ss++) {
            const int s = s0 + ss;
            float xr[8], vr[8];
            #pragma unroll
            for (int k = 0; k < 8; k++) { xr[k] = Xs[s*XP + k]; vr[k] = Xs[s*XP + 8 + k]; }
            #pragma unroll
            for (int c = 0; c < 4; c++) {
                const int i = j0 + c;
                float z = b0s[i], t = 0.f;
                #pragma unroll
                for (int k = 0; k < 8; k++) {
                    float w = W0s[i*W0P + k];
                    z = fmaf(w, xr[k], z);
                    t = fmaf(w, vr[k], t);
                }
                float h = tanhf(z);
                float d = 1.f - h*h;
                float e = d * t;                 // h1'
                float f = -2.f * h * t * e;      // h1''
                h1s[i*TBS + s] = h;
                e1s[i*TBS + s] = e;
                f1s[i*TBS + s] = f;
            }
        }
        __syncthreads();

        // ---- phase 2: Z2 = W1 h1, P = W1 h1', Q = W1 h1'' (fused, W1 loaded once) ----
        float az[4][4], ap[4][4], aq[4][4];
        #pragma unroll
        for (int c = 0; c < 4; c++)
            #pragma unroll
            for (int ss = 0; ss < 4; ss++) { az[c][ss]=0.f; ap[c][ss]=0.f; aq[c][ss]=0.f; }
        {
            const float* hp = h1s + s0;
            const float* ep = e1s + s0;
            const float* fp = f1s + s0;
            const float* w1r0 = W1s + (j0+0)*W1P;
            const float* w1r1 = W1s + (j0+1)*W1P;
            const float* w1r2 = W1s + (j0+2)*W1P;
            const float* w1r3 = W1s + (j0+3)*W1P;
            #pragma unroll 2
            for (int i = 0; i < HID; i++) {
                float4 hv = *(const float4*)(hp + i*TBS);
                float4 ev = *(const float4*)(ep + i*TBS);
                float4 fv = *(const float4*)(fp + i*TBS);
                float wv[4] = { w1r0[i], w1r1[i], w1r2[i], w1r3[i] };
                #pragma unroll
                for (int c = 0; c < 4; c++) {
                    const float w = wv[c];
                    az[c][0]=fmaf(w,hv.x,az[c][0]); az[c][1]=fmaf(w,hv.y,az[c][1]);
                    az[c][2]=fmaf(w,hv.z,az[c][2]); az[c][3]=fmaf(w,hv.w,az[c][3]);
                    ap[c][0]=fmaf(w,ev.x,ap[c][0]); ap[c][1]=fmaf(w,ev.y,ap[c][1]);
                    ap[c][2]=fmaf(w,ev.z,ap[c][2]); ap[c][3]=fmaf(w,ev.w,ap[c][3]);
                    aq[c][0]=fmaf(w,fv.x,aq[c][0]); aq[c][1]=fmaf(w,fv.y,aq[c][1]);
                    aq[c][2]=fmaf(w,fv.z,aq[c][2]); aq[c][3]=fmaf(w,fv.w,aq[c][3]);
                }
            }
        }
        __syncthreads();   // all phase-2 reads of h1/e1/f1 complete

        // ---- phase-2 epilogue: a = d2*w2 -> e1s ; hvv partials -> f1s[0..31][*] ----
        #pragma unroll
        for (int ss = 0; ss < 4; ss++) {
            const int s = s0 + ss;
            float hvp = 0.f;
            #pragma unroll
            for (int c = 0; c < 4; c++) {
                const int j = j0 + c;
                float z  = az[c][ss] + b1s[j];
                float h2 = tanhf(z);
                float d2 = 1.f - h2*h2;
                float w2j = w2s[j];
                float P = ap[c][ss], Q = aq[c][ss];
                hvp = fmaf(w2j, d2*Q - 2.f*h2*d2*P*P, hvp);
                e1s[j*TBS + s] = d2 * w2j;
            }
            f1s[jy*TBS + s] = hvp;
        }
        __syncthreads();
        if (tid < TBS) {
            float acc = 0.f;
            #pragma unroll
            for (int g = 0; g < 32; g++) acc += f1s[g*TBS + tid];
            hvs[tid] = acc;
        }
        __syncthreads();

        // ---- phase 3: U = W1^T a ; s_i = d1_i * U_i -> f1s ----
        float au[4][4];
        #pragma unroll
        for (int c = 0; c < 4; c++)
            #pragma unroll
            for (int ss = 0; ss < 4; ss++) au[c][ss] = 0.f;
        {
            const float* apnt = e1s + s0;
            #pragma unroll 2
            for (int j = 0; j < HID; j++) {
                float4 av = *(const float4*)(apnt + j*TBS);
                const float* w1r = W1s + j*W1P + j0;
                #pragma unroll
                for (int c = 0; c < 4; c++) {
                    const float w = w1r[c];
                    au[c][0]=fmaf(w,av.x,au[c][0]); au[c][1]=fmaf(w,av.y,au[c][1]);
                    au[c][2]=fmaf(w,av.z,au[c][2]); au[c][3]=fmaf(w,av.w,au[c][3]);
                }
            }
        }
        #pragma unroll
        for (int c = 0; c < 4; c++) {
            const int i = j0 + c;
            #pragma unroll
            for (int ss = 0; ss < 4; ss++) {
                const int s = s0 + ss;
                float h = h1s[i*TBS + s];
                f1s[i*TBS + s] = (1.f - h*h) * au[c][ss];
            }
        }
        __syncthreads();

        // ---- phase 4: g = W0^T s ----
        {
            float gq = 0.f;
            #pragma unroll 4
            for (int i = 0; i < HID; i++)
                gq = fmaf(W0s[i*W0P + qf], f1s[i*TBS + sf], gq);
            gbf[qf*TBS + sf] = gq;
        }
        __syncthreads();

        // ---- phase 5: Sherman-Morrison combine + store (coalesced) ----
        {
            float g[8];
            #pragma unroll
            for (int k = 0; k < 8; k++) g[k] = gbf[k*TBS + sf];
            float gg = 0.f;
            #pragma unroll
            for (int k = 0; k < 8; k++) gg = fmaf(g[k], g[k], gg);
            float xr[8], vr[8];
            #pragma unroll
            for (int k = 0; k < 8; k++) { xr[k] = Xs[sf*XP + k]; vr[k] = Xs[sf*XP + 8 + k]; }
            float gf = 0.f, fq = 0.f;
            #pragma unroll
            for (int q2 = 0; q2 < 8; q2++) {
                float fo = 0.f;
                #pragma unroll
                for (int k = 0; k < 8; k++) {
                    fo = fmaf(-Ds[q2*8+k], vr[k], fo);
                    fo = fmaf(-Ks[q2*8+k], xr[k], fo);
                }
                gf = fmaf(g[q2], fo, gf);
                if (q2 == qf) fq = fo;
            }
            float scale = (gf + hvs[sf]) / (1.f + gg);
            out[(base + sf)*8 + qf] = fq - g[qf]*scale;
        }
        __syncthreads();   // protect Xs before next tile's reload
    }
}

extern "C" void kernel_launch(void* const* d_in, const int* in_sizes, int n_in,
                              void* d_out, int out_size)
{
    const float* X  = (const float*)d_in[0];
    const float* Km = (const float*)d_in[1];
    const float* Dm = (const float*)d_in[2];
    const float* W0 = (const float*)d_in[3];
    const float* b0 = (const float*)d_in[4];
    const float* W1 = (const float*)d_in[5];
    const float* b1 = (const float*)d_in[6];
    const float* W2 = (const float*)d_in[7];
    // b2 (d_in[8]) does not affect the gradient/Hessian or the output.

    cudaFuncSetAttribute(dyn_kernel, cudaFuncAttributeMaxDynamicSharedMemorySize,
                         (int)SMEM_BYTES);
    dyn_kernel<<<GRID, NTHREADS, SMEM_BYTES>>>(X, Km, Dm, W0, b0, W1, b1, W2,
                                               (float*)d_out);
}

// round 2
// speedup vs baseline: 1.1543x; 1.1543x over previous
#include <cuda_runtime.h>
#include <math.h>

// Dynamics_79843442033036 — fused analytic grad/HVV kernel, f32x2-packed FFMA2.
// out_q = force_q - g_q * (g.force + v^T H v) / (1 + g.g)

typedef unsigned long long ull;

#define HID     128
#define DIMV    8
#define BATCHN  65536
#define TBS     64
#define NTILES  (BATCHN / TBS)
#define NTHREADS 512
#define GRID    152

#define W1P 132                    // float4-aligned pitch
#define XP  17
#define W0P 10

// shared memory layout (floats)
#define SM_W1   0
#define SM_H1   (SM_W1 + HID*W1P)        // 16896
#define SM_E1   (SM_H1 + HID*TBS)
#define SM_F1   (SM_E1 + HID*TBS)
#define SM_X    (SM_F1 + HID*TBS)
#define SM_W0   (SM_X + TBS*XP)
#define SM_B0   (SM_W0 + HID*W0P)
#define SM_B1   (SM_B0 + HID)
#define SM_W2   (SM_B1 + HID)
#define SM_K    (SM_W2 + HID)
#define SM_D    (SM_K + 64)
#define SM_G    (SM_D + 64)
#define SM_HVV  (SM_G + 8*TBS)
#define SM_TOTAL (SM_HVV + TBS)
#define SMEM_BYTES (SM_TOTAL * sizeof(float))

__device__ __forceinline__ ull pack2(float x, float y) {
    ull r; asm("mov.b64 %0, {%1,%2};" : "=l"(r) : "f"(x), "f"(y)); return r;
}
__device__ __forceinline__ float2 unpack2(ull v) {
    float2 r; asm("mov.b64 {%0,%1}, %2;" : "=f"(r.x), "=f"(r.y) : "l"(v)); return r;
}
__device__ __forceinline__ ull fma2(ull a, ull b, ull c) {
    ull r; asm("fma.rn.f32x2 %0, %1, %2, %3;" : "=l"(r) : "l"(a), "l"(b), "l"(c)); return r;
}
// fast tanh: 1 - 2/(e^{2z}+1). Saturates correctly at +-inf, rel err ~1e-6.
__device__ __forceinline__ float ftanh(float z) {
    float e = __expf(2.f * z);
    return 1.f - __fdividef(2.f, e + 1.f);
}

extern "C" __global__ void __launch_bounds__(NTHREADS, 1)
dyn_kernel(const float* __restrict__ X,  const float* __restrict__ Km,
           const float* __restrict__ Dm, const float* __restrict__ W0,
           const float* __restrict__ b0, const float* __restrict__ W1,
           const float* __restrict__ b1, const float* __restrict__ W2,
           float* __restrict__ out)
{
    extern __shared__ float sm[];
    float* W1s = sm + SM_W1;
    float* h1s = sm + SM_H1;
    float* e1s = sm + SM_E1;
    float* f1s = sm + SM_F1;
    float* Xs  = sm + SM_X;
    float* W0s = sm + SM_W0;
    float* b0s = sm + SM_B0;
    float* b1s = sm + SM_B1;
    float* w2s = sm + SM_W2;
    float* Ks  = sm + SM_K;
    float* Ds  = sm + SM_D;
    float* gbf = sm + SM_G;
    float* hvs = sm + SM_HVV;

    const int tid = threadIdx.x;

    // ---- one-time weight staging ----
    for (int idx = tid; idx < HID*HID; idx += NTHREADS) {
        int j = idx >> 7, i = idx & 127;
        W1s[j*W1P + i] = W1[idx];
    }
    for (int idx = tid; idx < HID*DIMV; idx += NTHREADS) {
        int i = idx >> 3, k = idx & 7;
        W0s[i*W0P + k] = W0[idx];
    }
    if (tid < HID) { b0s[tid] = b0[tid]; b1s[tid] = b1[tid]; w2s[tid] = W2[tid]; }
    if (tid < 64)  { Ks[tid] = Km[tid]; Ds[tid] = Dm[tid]; }
    __syncthreads();

    const int tx = tid & 15;
    const int jy = tid >> 4;
    const int s0 = tx * 4;
    const int j0 = jy * 4;
    const int qf = tid & 7;
    const int sf = tid >> 3;

    for (int tile = blockIdx.x; tile < NTILES; tile += gridDim.x) {
        const int base = tile * TBS;

        // ---- stage X tile ----
        for (int idx = tid; idx < TBS*16; idx += NTHREADS) {
            int s = idx >> 4, k = idx & 15;
            Xs[s*XP + k] = X[base*16 + idx];
        }
        __syncthreads();

        // ---- phase 1: h1, h1', h1'' ----
        #pragma unroll
        for (int ss = 0; ss < 4; ss++) {
            const int s = s0 + ss;
            float xr[8], vr[8];
            #pragma unroll
            for (int k = 0; k < 8; k++) { xr[k] = Xs[s*XP + k]; vr[k] = Xs[s*XP + 8 + k]; }
            #pragma unroll
            for (int c = 0; c < 4; c++) {
                const int i = j0 + c;
                float z = b0s[i], t = 0.f;
                #pragma unroll
                for (int k = 0; k < 8; k++) {
                    float w = W0s[i*W0P + k];
                    z = fmaf(w, xr[k], z);
                    t = fmaf(w, vr[k], t);
                }
                float h = ftanh(z);
                float d = 1.f - h*h;
                float e = d * t;
                float f = -2.f * h * t * e;
                h1s[i*TBS + s] = h;
                e1s[i*TBS + s] = e;
                f1s[i*TBS + s] = f;
            }
        }
        __syncthreads();

        // ---- phase 2: Z2 = W1 h1, P = W1 h1', Q = W1 h1'' (f32x2 packed) ----
        ull az2[4][2], ap2[4][2], aq2[4][2];
        #pragma unroll
        for (int c = 0; c < 4; c++) {
            az2[c][0]=0ull; az2[c][1]=0ull;
            ap2[c][0]=0ull; ap2[c][1]=0ull;
            aq2[c][0]=0ull; aq2[c][1]=0ull;
        }
        {
            const float* hp = h1s + s0;
            const float* ep = e1s + s0;
            const float* fp = f1s + s0;
            #pragma unroll 1
            for (int i = 0; i < HID; i += 4) {
                const float4 wr0 = *(const float4*)(W1s + (j0+0)*W1P + i);
                const float4 wr1 = *(const float4*)(W1s + (j0+1)*W1P + i);
                const float4 wr2 = *(const float4*)(W1s + (j0+2)*W1P + i);
                const float4 wr3 = *(const float4*)(W1s + (j0+3)*W1P + i);
                const float* wa0 = (const float*)&wr0;
                const float* wa1 = (const float*)&wr1;
                const float* wa2 = (const float*)&wr2;
                const float* wa3 = (const float*)&wr3;
                #pragma unroll
                for (int ii = 0; ii < 4; ii++) {
                    const ulonglong2 hv = *(const ulonglong2*)(hp + (i+ii)*TBS);
                    const ulonglong2 ev = *(const ulonglong2*)(ep + (i+ii)*TBS);
                    const ulonglong2 fv = *(const ulonglong2*)(fp + (i+ii)*TBS);
                    ull w;
                    w = pack2(wa0[ii], wa0[ii]);
                    az2[0][0]=fma2(w,hv.x,az2[0][0]); az2[0][1]=fma2(w,hv.y,az2[0][1]);
                    ap2[0][0]=fma2(w,ev.x,ap2[0][0]); ap2[0][1]=fma2(w,ev.y,ap2[0][1]);
                    aq2[0][0]=fma2(w,fv.x,aq2[0][0]); aq2[0][1]=fma2(w,fv.y,aq2[0][1]);
                    w = pack2(wa1[ii], wa1[ii]);
                    az2[1][0]=fma2(w,hv.x,az2[1][0]); az2[1][1]=fma2(w,hv.y,az2[1][1]);
                    ap2[1][0]=fma2(w,ev.x,ap2[1][0]); ap2[1][1]=fma2(w,ev.y,ap2[1][1]);
                    aq2[1][0]=fma2(w,fv.x,aq2[1][0]); aq2[1][1]=fma2(w,fv.y,aq2[1][1]);
                    w = pack2(wa2[ii], wa2[ii]);
                    az2[2][0]=fma2(w,hv.x,az2[2][0]); az2[2][1]=fma2(w,hv.y,az2[2][1]);
                    ap2[2][0]=fma2(w,ev.x,ap2[2][0]); ap2[2][1]=fma2(w,ev.y,ap2[2][1]);
                    aq2[2][0]=fma2(w,fv.x,aq2[2][0]); aq2[2][1]=fma2(w,fv.y,aq2[2][1]);
                    w = pack2(wa3[ii], wa3[ii]);
                    az2[3][0]=fma2(w,hv.x,az2[3][0]); az2[3][1]=fma2(w,hv.y,az2[3][1]);
                    ap2[3][0]=fma2(w,ev.x,ap2[3][0]); ap2[3][1]=fma2(w,ev.y,ap2[3][1]);
                    aq2[3][0]=fma2(w,fv.x,aq2[3][0]); aq2[3][1]=fma2(w,fv.y,aq2[3][1]);
                }
            }
        }
        __syncthreads();   // all phase-2 reads of h1/e1/f1 complete

        // ---- phase-2 epilogue: a = d2*w2 -> e1s ; hvv partials -> f1s ----
        {
            float hvp[4] = {0.f, 0.f, 0.f, 0.f};
            #pragma unroll
            for (int c = 0; c < 4; c++) {
                const int j = j0 + c;
                const float2 z01 = unpack2(az2[c][0]), z23 = unpack2(az2[c][1]);
                const float2 p01 = unpack2(ap2[c][0]), p23 = unpack2(ap2[c][1]);
                const float2 q01 = unpack2(aq2[c][0]), q23 = unpack2(aq2[c][1]);
                const float zz[4] = {z01.x, z01.y, z23.x, z23.y};
                const float pp[4] = {p01.x, p01.y, p23.x, p23.y};
                const float qq[4] = {q01.x, q01.y, q23.x, q23.y};
                const float w2j = w2s[j];
                const float bj  = b1s[j];
                #pragma unroll
                for (int ss = 0; ss < 4; ss++) {
                    float h2 = ftanh(zz[ss] + bj);
                    float d2 = 1.f - h2*h2;
                    float P = pp[ss], Q = qq[ss];
                    hvp[ss] = fmaf(w2j, d2*Q - 2.f*h2*d2*P*P, hvp[ss]);
                    e1s[j*TBS + s0 + ss] = d2 * w2j;
                }
            }
            #pragma unroll
            for (int ss = 0; ss < 4; ss++)
                f1s[jy*TBS + s0 + ss] = hvp[ss];
        }
        __syncthreads();
        if (tid < TBS) {
            float acc = 0.f;
            #pragma unroll
            for (int g = 0; g < 32; g++) acc += f1s[g*TBS + tid];
            hvs[tid] = acc;
        }
        __syncthreads();

        // ---- phase 3: U = W1^T a ; s_i = d1_i U_i -> f1s (f32x2 packed) ----
        ull au2[4][2];
        #pragma unroll
        for (int c = 0; c < 4; c++) { au2[c][0]=0ull; au2[c][1]=0ull; }
        {
            const float* apnt = e1s + s0;
            #pragma unroll 2
            for (int j = 0; j < HID; j++) {
                const ulonglong2 av = *(const ulonglong2*)(apnt + j*TBS);
                const float4 wv = *(const float4*)(W1s + j*W1P + j0);
                const float* wa = (const float*)&wv;
                ull w;
                w = pack2(wa[0], wa[0]);
                au2[0][0]=fma2(w,av.x,au2[0][0]); au2[0][1]=fma2(w,av.y,au2[0][1]);
                w = pack2(wa[1], wa[1]);
                au2[1][0]=fma2(w,av.x,au2[1][0]); au2[1][1]=fma2(w,av.y,au2[1][1]);
                w = pack2(wa[2], wa[2]);
                au2[2][0]=fma2(w,av.x,au2[2][0]); au2[2][1]=fma2(w,av.y,au2[2][1]);
                w = pack2(wa[3], wa[3]);
                au2[3][0]=fma2(w,av.x,au2[3][0]); au2[3][1]=fma2(w,av.y,au2[3][1]);
            }
        }
        #pragma unroll
        for (int c = 0; c < 4; c++) {
            const int i = j0 + c;
            const float2 u01 = unpack2(au2[c][0]), u23 = unpack2(au2[c][1]);
            const float uu[4] = {u01.x, u01.y, u23.x, u23.y};
            #pragma unroll
            for (int ss = 0; ss < 4; ss++) {
                const int s = s0 + ss;
                float h = h1s[i*TBS + s];
                f1s[i*TBS + s] = (1.f - h*h) * uu[ss];
            }
        }
        __syncthreads();

        // ---- phase 4: g = W0^T s ----
        {
            float gq = 0.f;
            #pragma unroll 4
            for (int i = 0; i < HID; i++)
                gq = fmaf(W0s[i*W0P + qf], f1s[i*TBS + sf], gq);
            gbf[qf*TBS + sf] = gq;
        }
        __syncthreads();

        // ---- phase 5: Sherman-Morrison combine + coalesced store ----
        {
            float g[8];
            #pragma unroll
            for (int k = 0; k < 8; k++) g[k] = gbf[k*TBS + sf];
            float gg = 0.f;
            #pragma unroll
            for (int k = 0; k < 8; k++) gg = fmaf(g[k], g[k], gg);
            float xr[8], vr[8];
            #pragma unroll
            for (int k = 0; k < 8; k++) { xr[k] = Xs[sf*XP + k]; vr[k] = Xs[sf*XP + 8 + k]; }
            float gf = 0.f, fq = 0.f;
            #pragma unroll
            for (int q2 = 0; q2 < 8; q2++) {
                float fo = 0.f;
                #pragma unroll
                for (int k = 0; k < 8; k++) {
                    fo = fmaf(-Ds[q2*8+k], vr[k], fo);
                    fo = fmaf(-Ks[q2*8+k], xr[k], fo);
                }
                gf = fmaf(g[q2], fo, gf);
                if (q2 == qf) fq = fo;
            }
            float scale = (gf + hvs[sf]) / (1.f + gg);
            out[(base + sf)*8 + qf] = fq - g[qf]*scale;
        }
        __syncthreads();
    }
}

extern "C" void kernel_launch(void* const* d_in, const int* in_sizes, int n_in,
                              void* d_out, int out_size)
{
    const float* X  = (const float*)d_in[0];
    const float* Km = (const float*)d_in[1];
    const float* Dm = (const float*)d_in[2];
    const float* W0 = (const float*)d_in[3];
    const float* b0 = (const float*)d_in[4];
    const float* W1 = (const float*)d_in[5];
    const float* b1 = (const float*)d_in[6];
    const float* W2 = (const float*)d_in[7];

    cudaFuncSetAttribute(dyn_kernel, cudaFuncAttributeMaxDynamicSharedMemorySize,
                         (int)SMEM_BYTES);
    dyn_kernel<<<GRID, NTHREADS, SMEM_BYTES>>>(X, Km, Dm, W0, b0, W1, b1, W2,
                                               (float*)d_out);
}

// round 3
// speedup vs baseline: 1.1894x; 1.0304x over previous
#include <cuda_runtime.h>
#include <math.h>

// Dynamics_79843442033036 — fused analytic grad/HVV kernel.
// f32x2 FFMA2 + dual-group software pipelining (2 virtual CTAs per SM
// sharing one W1 copy, independent named barriers).

typedef unsigned long long ull;

#define HID     128
#define DIMV    8
#define BATCHN  65536
#define TBS     32                  // samples per group tile
#define NTILES  (BATCHN / TBS)      // 2048
#define NTHREADS 512
#define GTHREADS 256
#define GRID    152
#define NWORKERS (GRID * 2)         // 304

#define W1P 132
#define XP  17
#define W0P 10

// ---- shared weights (floats) ----
#define SM_W1   0
#define SM_W0   (SM_W1 + HID*W1P)        // 16896
#define SM_B0   (SM_W0 + HID*W0P)
#define SM_B1   (SM_B0 + HID)
#define SM_W2   (SM_B1 + HID)
#define SM_K    (SM_W2 + HID)
#define SM_D    (SM_K + 64)
#define SM_GRPBASE (SM_D + 64)
// ---- per-group region (floats) ----
#define G_H1    0
#define G_E1    (G_H1 + HID*TBS)
#define G_F1    (G_E1 + HID*TBS)
#define G_X     (G_F1 + HID*TBS)         // [32][17]
#define G_G     (G_X + TBS*XP)           // [8][32]
#define G_HVV   (G_G + 8*TBS)            // [32]
#define G_SIZE  (G_HVV + TBS)
#define SM_TOTAL (SM_GRPBASE + 2*G_SIZE)
#define SMEM_BYTES (SM_TOTAL * sizeof(float))

__device__ __forceinline__ ull pack2(float x, float y) {
    ull r; asm("mov.b64 %0, {%1,%2};" : "=l"(r) : "f"(x), "f"(y)); return r;
}
__device__ __forceinline__ float2 unpack2(ull v) {
    float2 r; asm("mov.b64 {%0,%1}, %2;" : "=f"(r.x), "=f"(r.y) : "l"(v)); return r;
}
__device__ __forceinline__ ull fma2(ull a, ull b, ull c) {
    ull r; asm("fma.rn.f32x2 %0, %1, %2, %3;" : "=l"(r) : "l"(a), "l"(b), "l"(c)); return r;
}
// fast tanh: 1 - 2/(e^{2z}+1). Correct saturation, rel err ~1e-6.
__device__ __forceinline__ float ftanh(float z) {
    float e = __expf(2.f * z);
    return 1.f - __fdividef(2.f, e + 1.f);
}

extern "C" __global__ void __launch_bounds__(NTHREADS, 1)
dyn_kernel(const float* __restrict__ X,  const float* __restrict__ Km,
           const float* __restrict__ Dm, const float* __restrict__ W0,
           const float* __restrict__ b0, const float* __restrict__ W1,
           const float* __restrict__ b1, const float* __restrict__ W2,
           float* __restrict__ out)
{
    extern __shared__ float sm[];
    float* W1s = sm + SM_W1;
    float* W0s = sm + SM_W0;
    float* b0s = sm + SM_B0;
    float* b1s = sm + SM_B1;
    float* w2s = sm + SM_W2;
    float* Ks  = sm + SM_K;
    float* Ds  = sm + SM_D;

    const int tid   = threadIdx.x;
    const int group = tid >> 8;          // 0 or 1
    const int gtid  = tid & 255;
    const int gbar  = group + 1;         // named barrier id 1 or 2

    float* gbase = sm + SM_GRPBASE + group * G_SIZE;
    float* h1s = gbase + G_H1;
    float* e1s = gbase + G_E1;
    float* f1s = gbase + G_F1;
    float* Xs  = gbase + G_X;
    float* gbf = gbase + G_G;
    float* hvs = gbase + G_HVV;

    // ---- one-time weight staging (whole CTA) ----
    for (int idx = tid; idx < HID*HID; idx += NTHREADS) {
        int j = idx >> 7, i = idx & 127;
        W1s[j*W1P + i] = W1[idx];
    }
    for (int idx = tid; idx < HID*DIMV; idx += NTHREADS) {
        int i = idx >> 3, k = idx & 7;
        W0s[i*W0P + k] = W0[idx];
    }
    if (tid < HID) { b0s[tid] = b0[tid]; b1s[tid] = b1[tid]; w2s[tid] = W2[tid]; }
    if (tid < 64)  { Ks[tid] = Km[tid]; Ds[tid] = Dm[tid]; }
    __syncthreads();

    const int tx = gtid & 7;            // 8 sample-groups x 4 samples
    const int jy = gtid >> 3;           // 32 hidden-groups x 4 rows
    const int s0 = tx * 4;
    const int j0 = jy * 4;
    const int qf = gtid & 7;
    const int sf = gtid >> 3;           // 0..31

    const int worker = blockIdx.x * 2 + group;

    for (int tile = worker; tile < NTILES; tile += NWORKERS) {
        const int base = tile * TBS;

        // ---- stage X tile ----
        for (int idx = gtid; idx < TBS*16; idx += GTHREADS) {
            int s = idx >> 4, k = idx & 15;
            Xs[s*XP + k] = X[base*16 + idx];
        }
        asm volatile("bar.sync %0, 256;" :: "r"(gbar) : "memory");

        // ---- phase 1: h1, h1', h1'' ----
        #pragma unroll
        for (int ss = 0; ss < 4; ss++) {
            const int s = s0 + ss;
            float xr[8], vr[8];
            #pragma unroll
            for (int k = 0; k < 8; k++) { xr[k] = Xs[s*XP + k]; vr[k] = Xs[s*XP + 8 + k]; }
            #pragma unroll
            for (int c = 0; c < 4; c++) {
                const int i = j0 + c;
                float z = b0s[i], t = 0.f;
                #pragma unroll
                for (int k = 0; k < 8; k++) {
                    float w = W0s[i*W0P + k];
                    z = fmaf(w, xr[k], z);
                    t = fmaf(w, vr[k], t);
                }
                float h = ftanh(z);
                float d = 1.f - h*h;
                float e = d * t;
                float f = -2.f * h * t * e;
                h1s[i*TBS + s] = h;
                e1s[i*TBS + s] = e;
                f1s[i*TBS + s] = f;
            }
        }
        asm volatile("bar.sync %0, 256;" :: "r"(gbar) : "memory");

        // ---- phase 2: Z2 = W1 h1, P = W1 h1', Q = W1 h1'' (f32x2) ----
        ull az2[4][2], ap2[4][2], aq2[4][2];
        #pragma unroll
        for (int c = 0; c < 4; c++) {
            az2[c][0]=0ull; az2[c][1]=0ull;
            ap2[c][0]=0ull; ap2[c][1]=0ull;
            aq2[c][0]=0ull; aq2[c][1]=0ull;
        }
        {
            const float* hp = h1s + s0;
            const float* ep = e1s + s0;
            const float* fp = f1s + s0;
            #pragma unroll 1
            for (int i = 0; i < HID; i += 4) {
                const float4 wr0 = *(const float4*)(W1s + (j0+0)*W1P + i);
                const float4 wr1 = *(const float4*)(W1s + (j0+1)*W1P + i);
                const float4 wr2 = *(const float4*)(W1s + (j0+2)*W1P + i);
                const float4 wr3 = *(const float4*)(W1s + (j0+3)*W1P + i);
                const float* wa0 = (const float*)&wr0;
                const float* wa1 = (const float*)&wr1;
                const float* wa2 = (const float*)&wr2;
                const float* wa3 = (const float*)&wr3;
                #pragma unroll
                for (int ii = 0; ii < 4; ii++) {
                    const ulonglong2 hv = *(const ulonglong2*)(hp + (i+ii)*TBS);
                    const ulonglong2 ev = *(const ulonglong2*)(ep + (i+ii)*TBS);
                    const ulonglong2 fv = *(const ulonglong2*)(fp + (i+ii)*TBS);
                    ull w;
                    w = pack2(wa0[ii], wa0[ii]);
                    az2[0][0]=fma2(w,hv.x,az2[0][0]); az2[0][1]=fma2(w,hv.y,az2[0][1]);
                    ap2[0][0]=fma2(w,ev.x,ap2[0][0]); ap2[0][1]=fma2(w,ev.y,ap2[0][1]);
                    aq2[0][0]=fma2(w,fv.x,aq2[0][0]); aq2[0][1]=fma2(w,fv.y,aq2[0][1]);
                    w = pack2(wa1[ii], wa1[ii]);
                    az2[1][0]=fma2(w,hv.x,az2[1][0]); az2[1][1]=fma2(w,hv.y,az2[1][1]);
                    ap2[1][0]=fma2(w,ev.x,ap2[1][0]); ap2[1][1]=fma2(w,ev.y,ap2[1][1]);
                    aq2[1][0]=fma2(w,fv.x,aq2[1][0]); aq2[1][1]=fma2(w,fv.y,aq2[1][1]);
                    w = pack2(wa2[ii], wa2[ii]);
                    az2[2][0]=fma2(w,hv.x,az2[2][0]); az2[2][1]=fma2(w,hv.y,az2[2][1]);
                    ap2[2][0]=fma2(w,ev.x,ap2[2][0]); ap2[2][1]=fma2(w,ev.y,ap2[2][1]);
                    aq2[2][0]=fma2(w,fv.x,aq2[2][0]); aq2[2][1]=fma2(w,fv.y,aq2[2][1]);
                    w = pack2(wa3[ii], wa3[ii]);
                    az2[3][0]=fma2(w,hv.x,az2[3][0]); az2[3][1]=fma2(w,hv.y,az2[3][1]);
                    ap2[3][0]=fma2(w,ev.x,ap2[3][0]); ap2[3][1]=fma2(w,ev.y,ap2[3][1]);
                    aq2[3][0]=fma2(w,fv.x,aq2[3][0]); aq2[3][1]=fma2(w,fv.y,aq2[3][1]);
                }
            }
        }
        asm volatile("bar.sync %0, 256;" :: "r"(gbar) : "memory");

        // ---- phase-2 epilogue: a = d2*w2 -> e1s ; hvv partials -> f1s ----
        {
            float hvp[4] = {0.f, 0.f, 0.f, 0.f};
            #pragma unroll
            for (int c = 0; c < 4; c++) {
                const int j = j0 + c;
                const float2 z01 = unpack2(az2[c][0]), z23 = unpack2(az2[c][1]);
                const float2 p01 = unpack2(ap2[c][0]), p23 = unpack2(ap2[c][1]);
                const float2 q01 = unpack2(aq2[c][0]), q23 = unpack2(aq2[c][1]);
                const float zz[4] = {z01.x, z01.y, z23.x, z23.y};
                const float pp[4] = {p01.x, p01.y, p23.x, p23.y};
                const float qq[4] = {q01.x, q01.y, q23.x, q23.y};
                const float w2j = w2s[j];
                const float bj  = b1s[j];
                #pragma unroll
                for (int ss = 0; ss < 4; ss++) {
                    float h2 = ftanh(zz[ss] + bj);
                    float d2 = 1.f - h2*h2;
                    float P = pp[ss], Q = qq[ss];
                    hvp[ss] = fmaf(w2j, d2*Q - 2.f*h2*d2*P*P, hvp[ss]);
                    e1s[j*TBS + s0 + ss] = d2 * w2j;
                }
            }
            #pragma unroll
            for (int ss = 0; ss < 4; ss++)
                f1s[jy*TBS + s0 + ss] = hvp[ss];
        }
        asm volatile("bar.sync %0, 256;" :: "r"(gbar) : "memory");
        if (gtid < TBS) {
            float acc = 0.f;
            #pragma unroll
            for (int g = 0; g < 32; g++) acc += f1s[g*TBS + gtid];
            hvs[gtid] = acc;
        }
        asm volatile("bar.sync %0, 256;" :: "r"(gbar) : "memory");

        // ---- phase 3: U = W1^T a ; s_i = d1_i U_i -> f1s ----
        ull au2[4][2];
        #pragma unroll
        for (int c = 0; c < 4; c++) { au2[c][0]=0ull; au2[c][1]=0ull; }
        {
            const float* apnt = e1s + s0;
            #pragma unroll 2
            for (int j = 0; j < HID; j++) {
                const ulonglong2 av = *(const ulonglong2*)(apnt + j*TBS);
                const float4 wv = *(const float4*)(W1s + j*W1P + j0);
                const float* wa = (const float*)&wv;
                ull w;
                w = pack2(wa[0], wa[0]);
                au2[0][0]=fma2(w,av.x,au2[0][0]); au2[0][1]=fma2(w,av.y,au2[0][1]);
                w = pack2(wa[1], wa[1]);
                au2[1][0]=fma2(w,av.x,au2[1][0]); au2[1][1]=fma2(w,av.y,au2[1][1]);
                w = pack2(wa[2], wa[2]);
                au2[2][0]=fma2(w,av.x,au2[2][0]); au2[2][1]=fma2(w,av.y,au2[2][1]);
                w = pack2(wa[3], wa[3]);
                au2[3][0]=fma2(w,av.x,au2[3][0]); au2[3][1]=fma2(w,av.y,au2[3][1]);
            }
        }
        #pragma unroll
        for (int c = 0; c < 4; c++) {
            const int i = j0 + c;
            const float2 u01 = unpack2(au2[c][0]), u23 = unpack2(au2[c][1]);
            const float uu[4] = {u01.x, u01.y, u23.x, u23.y};
            #pragma unroll
            for (int ss = 0; ss < 4; ss++) {
                const int s = s0 + ss;
                float h = h1s[i*TBS + s];
                f1s[i*TBS + s] = (1.f - h*h) * uu[ss];
            }
        }
        asm volatile("bar.sync %0, 256;" :: "r"(gbar) : "memory");

        // ---- phase 4: g = W0^T s ----
        {
            float gq = 0.f;
            #pragma unroll 4
            for (int i = 0; i < HID; i++)
                gq = fmaf(W0s[i*W0P + qf], f1s[i*TBS + sf], gq);
            gbf[qf*TBS + sf] = gq;
        }
        asm volatile("bar.sync %0, 256;" :: "r"(gbar) : "memory");

        // ---- phase 5: Sherman-Morrison combine + coalesced store ----
        {
            float g[8];
            #pragma unroll
            for (int k = 0; k < 8; k++) g[k] = gbf[k*TBS + sf];
            float gg = 0.f;
            #pragma unroll
            for (int k = 0; k < 8; k++) gg = fmaf(g[k], g[k], gg);
            float xr[8], vr[8];
            #pragma unroll
            for (int k = 0; k < 8; k++) { xr[k] = Xs[sf*XP + k]; vr[k] = Xs[sf*XP + 8 + k]; }
            float gf = 0.f, fq = 0.f;
            #pragma unroll
            for (int q2 = 0; q2 < 8; q2++) {
                float fo = 0.f;
                #pragma unroll
                for (int k = 0; k < 8; k++) {
                    fo = fmaf(-Ds[q2*8+k], vr[k], fo);
                    fo = fmaf(-Ks[q2*8+k], xr[k], fo);
                }
                gf = fmaf(g[q2], fo, gf);
                if (q2 == qf) fq = fo;
            }
            float scale = (gf + hvs[sf]) / (1.f + gg);
            out[(base + sf)*8 + qf] = fq - g[qf]*scale;
        }
        asm volatile("bar.sync %0, 256;" :: "r"(gbar) : "memory");
    }
}

extern "C" void kernel_launch(void* const* d_in, const int* in_sizes, int n_in,
                              void* d_out, int out_size)
{
    const float* X  = (const float*)d_in[0];
    const float* Km = (const float*)d_in[1];
    const float* Dm = (const float*)d_in[2];
    const float* W0 = (const float*)d_in[3];
    const float* b0 = (const float*)d_in[4];
    const float* W1 = (const float*)d_in[5];
    const float* b1 = (const float*)d_in[6];
    const float* W2 = (const float*)d_in[7];

    cudaFuncSetAttribute(dyn_kernel, cudaFuncAttributeMaxDynamicSharedMemorySize,
                         (int)SMEM_BYTES);
    dyn_kernel<<<GRID, NTHREADS, SMEM_BYTES>>>(X, Km, Dm, W0, b0, W1, b1, W2,
                                               (float*)d_out);
}

// round 4
// speedup vs baseline: 1.4020x; 1.1787x over previous
#include <cuda_runtime.h>
#include <math.h>

// Dynamics_79843442033036 — fused analytic grad/HVV kernel.
// f32x2 FFMA2, dual-group pipelining, Q-matvec eliminated algebraically:
//   hvv Q-term = (W1^T a)^T h1'' = U . h1''  (U already needed for backprop).

typedef unsigned long long ull;

#define HID     128
#define DIMV    8
#define BATCHN  65536
#define TBS     32
#define NTILES  (BATCHN / TBS)      // 2048
#define NTHREADS 512
#define GTHREADS 256
#define GRID    152
#define NWORKERS (GRID * 2)

#define W1P 132
#define XP  17
#define W0P 10
#define HVP 33                      // hvv-partial pitch (conflict-free reduce)

// ---- shared weights (float offsets) ----
#define SM_W1   0
#define SM_W0   (SM_W1 + HID*W1P)          // 16896
#define SM_W0D  (SM_W0 + HID*W0P)          // 18176 (even -> 8B aligned)
#define SM_B0   (SM_W0D + HID*DIMV*2)      // 20224
#define SM_B1   (SM_B0 + HID)
#define SM_W2   (SM_B1 + HID)
#define SM_K    (SM_W2 + HID)
#define SM_D    (SM_K + 64)
#define SM_GRPBASE (SM_D + 64)             // 20736
// ---- per-group region ----
#define G_H1    0
#define G_E1    (G_H1 + HID*TBS)
#define G_F1    (G_E1 + HID*TBS)
#define G_X     (G_F1 + HID*TBS)           // [32][17]
#define G_G     (G_X + TBS*XP)             // [8][32]
#define G_HVV   (G_G + 8*TBS)              // [32]
#define G_HVP   (G_HVV + TBS)              // [32][33]
#define G_SIZE  (G_HVP + 32*HVP)           // 14176 (even)
#define SM_TOTAL (SM_GRPBASE + 2*G_SIZE)
#define SMEM_BYTES (SM_TOTAL * sizeof(float))

__device__ __forceinline__ ull pack2(float x, float y) {
    ull r; asm("mov.b64 %0, {%1,%2};" : "=l"(r) : "f"(x), "f"(y)); return r;
}
__device__ __forceinline__ float2 unpack2(ull v) {
    float2 r; asm("mov.b64 {%0,%1}, %2;" : "=f"(r.x), "=f"(r.y) : "l"(v)); return r;
}
__device__ __forceinline__ ull fma2(ull a, ull b, ull c) {
    ull r; asm("fma.rn.f32x2 %0, %1, %2, %3;" : "=l"(r) : "l"(a), "l"(b), "l"(c)); return r;
}
// fast tanh: 1 - 2/(e^{2z}+1). Correct saturation, rel err ~1e-6.
__device__ __forceinline__ float ftanh(float z) {
    float e = __expf(2.f * z);
    return 1.f - __fdividef(2.f, e + 1.f);
}

extern "C" __global__ void __launch_bounds__(NTHREADS, 1)
dyn_kernel(const float* __restrict__ X,  const float* __restrict__ Km,
           const float* __restrict__ Dm, const float* __restrict__ W0,
           const float* __restrict__ b0, const float* __restrict__ W1,
           const float* __restrict__ b1, const float* __restrict__ W2,
           float* __restrict__ out)
{
    extern __shared__ float sm[];
    float* W1s = sm + SM_W1;
    float* W0s = sm + SM_W0;
    float* W0d = sm + SM_W0D;          // duplicated pairs (w,w) as f32x2
    float* b0s = sm + SM_B0;
    float* b1s = sm + SM_B1;
    float* w2s = sm + SM_W2;
    float* Ks  = sm + SM_K;
    float* Ds  = sm + SM_D;

    const int tid   = threadIdx.x;
    const int group = tid >> 8;
    const int gtid  = tid & 255;
    const int gbar  = group + 1;

    float* gbase = sm + SM_GRPBASE + group * G_SIZE;
    float* h1s = gbase + G_H1;
    float* e1s = gbase + G_E1;
    float* f1s = gbase + G_F1;
    float* Xs  = gbase + G_X;
    float* gbf = gbase + G_G;
    float* hvs = gbase + G_HVV;
    float* hvp_s = gbase + G_HVP;

    // ---- one-time weight staging (whole CTA) ----
    for (int idx = tid; idx < HID*HID; idx += NTHREADS) {
        int j = idx >> 7, i = idx & 127;
        W1s[j*W1P + i] = W1[idx];
    }
    for (int idx = tid; idx < HID*DIMV; idx += NTHREADS) {
        int i = idx >> 3, k = idx & 7;
        float w = W0[idx];
        W0s[i*W0P + k] = w;
        W0d[idx*2]     = w;
        W0d[idx*2 + 1] = w;
    }
    if (tid < HID) { b0s[tid] = b0[tid]; b1s[tid] = b1[tid]; w2s[tid] = W2[tid]; }
    if (tid < 64)  { Ks[tid] = Km[tid]; Ds[tid] = Dm[tid]; }
    __syncthreads();

    const int tx = gtid & 7;            // 8 sample-groups x 4 samples
    const int jy = gtid >> 3;           // 32 hidden-groups x 4 rows
    const int s0 = tx * 4;
    const int j0 = jy * 4;
    const int qf = gtid & 7;
    const int sf = gtid >> 3;           // 0..31

    const int worker = blockIdx.x * 2 + group;

    for (int tile = worker; tile < NTILES; tile += NWORKERS) {
        const int base = tile * TBS;

        // ---- stage X tile ----
        for (int idx = gtid; idx < TBS*16; idx += GTHREADS) {
            int s = idx >> 4, k = idx & 15;
            Xs[s*XP + k] = X[base*16 + idx];
        }
        asm volatile("bar.sync %0, 256;" :: "r"(gbar) : "memory");

        // ---- phase 1: h1 (h), h1' (e), h1'' (f) ----
        #pragma unroll
        for (int ss = 0; ss < 4; ss++) {
            const int s = s0 + ss;
            float xr[8], vr[8];
            #pragma unroll
            for (int k = 0; k < 8; k++) { xr[k] = Xs[s*XP + k]; vr[k] = Xs[s*XP + 8 + k]; }
            #pragma unroll
            for (int c = 0; c < 4; c++) {
                const int i = j0 + c;
                float z = b0s[i], t = 0.f;
                #pragma unroll
                for (int k = 0; k < 8; k++) {
                    float w = W0s[i*W0P + k];
                    z = fmaf(w, xr[k], z);
                    t = fmaf(w, vr[k], t);
                }
                float h = ftanh(z);
                float d = 1.f - h*h;
                float e = d * t;
                float f = -2.f * h * t * e;
                h1s[i*TBS + s] = h;
                e1s[i*TBS + s] = e;
                f1s[i*TBS + s] = f;
            }
        }
        asm volatile("bar.sync %0, 256;" :: "r"(gbar) : "memory");

        // ---- phase 2: z2 = W1 h1, P = W1 h1'  (2 matvecs, f32x2) ----
        ull az2[4][2], ap2[4][2];
        #pragma unroll
        for (int c = 0; c < 4; c++) {
            az2[c][0]=0ull; az2[c][1]=0ull;
            ap2[c][0]=0ull; ap2[c][1]=0ull;
        }
        {
            const float* hp = h1s + s0;
            const float* ep = e1s + s0;
            #pragma unroll 1
            for (int i = 0; i < HID; i += 4) {
                const float4 wr0 = *(const float4*)(W1s + (j0+0)*W1P + i);
                const float4 wr1 = *(const float4*)(W1s + (j0+1)*W1P + i);
                const float4 wr2 = *(const float4*)(W1s + (j0+2)*W1P + i);
                const float4 wr3 = *(const float4*)(W1s + (j0+3)*W1P + i);
                const float* wa0 = (const float*)&wr0;
                const float* wa1 = (const float*)&wr1;
                const float* wa2 = (const float*)&wr2;
                const float* wa3 = (const float*)&wr3;
                #pragma unroll
                for (int ii = 0; ii < 4; ii++) {
                    const ulonglong2 hv = *(const ulonglong2*)(hp + (i+ii)*TBS);
                    const ulonglong2 ev = *(const ulonglong2*)(ep + (i+ii)*TBS);
                    ull w;
                    w = pack2(wa0[ii], wa0[ii]);
                    az2[0][0]=fma2(w,hv.x,az2[0][0]); az2[0][1]=fma2(w,hv.y,az2[0][1]);
                    ap2[0][0]=fma2(w,ev.x,ap2[0][0]); ap2[0][1]=fma2(w,ev.y,ap2[0][1]);
                    w = pack2(wa1[ii], wa1[ii]);
                    az2[1][0]=fma2(w,hv.x,az2[1][0]); az2[1][1]=fma2(w,hv.y,az2[1][1]);
                    ap2[1][0]=fma2(w,ev.x,ap2[1][0]); ap2[1][1]=fma2(w,ev.y,ap2[1][1]);
                    w = pack2(wa2[ii], wa2[ii]);
                    az2[2][0]=fma2(w,hv.x,az2[2][0]); az2[2][1]=fma2(w,hv.y,az2[2][1]);
                    ap2[2][0]=fma2(w,ev.x,ap2[2][0]); ap2[2][1]=fma2(w,ev.y,ap2[2][1]);
                    w = pack2(wa3[ii], wa3[ii]);
                    az2[3][0]=fma2(w,hv.x,az2[3][0]); az2[3][1]=fma2(w,hv.y,az2[3][1]);
                    ap2[3][0]=fma2(w,ev.x,ap2[3][0]); ap2[3][1]=fma2(w,ev.y,ap2[3][1]);
                }
            }
        }
        asm volatile("bar.sync %0, 256;" :: "r"(gbar) : "memory");  // GEMM reads done

        // ---- phase-2 epilogue: a = d2*w2 -> e1s ; P-term hvv partial in regs ----
        float hvp[4] = {0.f, 0.f, 0.f, 0.f};
        {
            #pragma unroll
            for (int c = 0; c < 4; c++) {
                const int j = j0 + c;
                const float2 z01 = unpack2(az2[c][0]), z23 = unpack2(az2[c][1]);
                const float2 p01 = unpack2(ap2[c][0]), p23 = unpack2(ap2[c][1]);
                const float zz[4] = {z01.x, z01.y, z23.x, z23.y};
                const float pp[4] = {p01.x, p01.y, p23.x, p23.y};
                const float w2j = w2s[j];
                const float bj  = b1s[j];
                #pragma unroll
                for (int ss = 0; ss < 4; ss++) {
                    float h2 = ftanh(zz[ss] + bj);
                    float d2 = 1.f - h2*h2;
                    float P = pp[ss];
                    hvp[ss] = fmaf(-2.f*w2j, h2*d2*P*P, hvp[ss]);
                    e1s[j*TBS + s0 + ss] = d2 * w2j;
                }
            }
        }
        asm volatile("bar.sync %0, 256;" :: "r"(gbar) : "memory");  // a ready

        // ---- phase 3: U = W1^T a (f32x2) ----
        ull au2[4][2];
        #pragma unroll
        for (int c = 0; c < 4; c++) { au2[c][0]=0ull; au2[c][1]=0ull; }
        {
            const float* apnt = e1s + s0;
            #pragma unroll 2
            for (int j = 0; j < HID; j++) {
                const ulonglong2 av = *(const ulonglong2*)(apnt + j*TBS);
                const float4 wv = *(const float4*)(W1s + j*W1P + j0);
                const float* wa = (const float*)&wv;
                ull w;
                w = pack2(wa[0], wa[0]);
                au2[0][0]=fma2(w,av.x,au2[0][0]); au2[0][1]=fma2(w,av.y,au2[0][1]);
                w = pack2(wa[1], wa[1]);
                au2[1][0]=fma2(w,av.x,au2[1][0]); au2[1][1]=fma2(w,av.y,au2[1][1]);
                w = pack2(wa[2], wa[2]);
                au2[2][0]=fma2(w,av.x,au2[2][0]); au2[2][1]=fma2(w,av.y,au2[2][1]);
                w = pack2(wa[3], wa[3]);
                au2[3][0]=fma2(w,av.x,au2[3][0]); au2[3][1]=fma2(w,av.y,au2[3][1]);
            }
        }
        // ---- phase-3 epilogue: Q-term hvv += U.h1'' ; s = d1*U -> f1s ----
        #pragma unroll
        for (int c = 0; c < 4; c++) {
            const int i = j0 + c;
            const float2 u01 = unpack2(au2[c][0]), u23 = unpack2(au2[c][1]);
            const float uu[4] = {u01.x, u01.y, u23.x, u23.y};
            #pragma unroll
            for (int ss = 0; ss < 4; ss++) {
                const int s = s0 + ss;
                float fpp = f1s[i*TBS + s];          // h1''
                hvp[ss] = fmaf(uu[ss], fpp, hvp[ss]);
                float h = h1s[i*TBS + s];
                f1s[i*TBS + s] = (1.f - h*h) * uu[ss];
            }
        }
        #pragma unroll
        for (int ss = 0; ss < 4; ss++)
            hvp_s[jy*HVP + s0 + ss] = hvp[ss];
        asm volatile("bar.sync %0, 256;" :: "r"(gbar) : "memory");

        // ---- hvv reduction (32 threads, conflict-free pitch 33) ----
        if (gtid < TBS) {
            float acc = 0.f;
            #pragma unroll
            for (int g = 0; g < 32; g++) acc += hvp_s[g*HVP + gtid];
            hvs[gtid] = acc;
        }
        // ---- phase 4: g = W0^T s (f32x2, packed W0d, 128 threads) ----
        if (gtid < 128) {
            const int q  = gtid & 7;
            const int sp = gtid >> 3;        // sample pair 0..15
            ull acc = 0ull;
            const ull* w0dp = (const ull*)(W0d) + q;
            const float* fp = f1s + 2*sp;
            #pragma unroll 4
            for (int i = 0; i < HID; i++)
                acc = fma2(w0dp[i*8], *(const ull*)(fp + i*TBS), acc);
            float2 gv = unpack2(acc);
            gbf[q*TBS + 2*sp]     = gv.x;
            gbf[q*TBS + 2*sp + 1] = gv.y;
        }
        asm volatile("bar.sync %0, 256;" :: "r"(gbar) : "memory");

        // ---- phase 5: Sherman-Morrison combine + coalesced store ----
        {
            float g[8];
            #pragma unroll
            for (int k = 0; k < 8; k++) g[k] = gbf[k*TBS + sf];
            float gg = 0.f;
            #pragma unroll
            for (int k = 0; k < 8; k++) gg = fmaf(g[k], g[k], gg);
            float xr[8], vr[8];
            #pragma unroll
            for (int k = 0; k < 8; k++) { xr[k] = Xs[sf*XP + k]; vr[k] = Xs[sf*XP + 8 + k]; }
            float gf = 0.f, fq = 0.f;
            #pragma unroll
            for (int q2 = 0; q2 < 8; q2++) {
                float fo = 0.f;
                #pragma unroll
                for (int k = 0; k < 8; k++) {
                    fo = fmaf(-Ds[q2*8+k], vr[k], fo);
                    fo = fmaf(-Ks[q2*8+k], xr[k], fo);
                }
                gf = fmaf(g[q2], fo, gf);
                if (q2 == qf) fq = fo;
            }
            float scale = (gf + hvs[sf]) / (1.f + gg);
            out[(base + sf)*8 + qf] = fq - g[qf]*scale;
        }
        asm volatile("bar.sync %0, 256;" :: "r"(gbar) : "memory");
    }
}

extern "C" void kernel_launch(void* const* d_in, const int* in_sizes, int n_in,
                              void* d_out, int out_size)
{
    const float* X  = (const float*)d_in[0];
    const float* Km = (const float*)d_in[1];
    const float* Dm = (const float*)d_in[2];
    const float* W0 = (const float*)d_in[3];
    const float* b0 = (const float*)d_in[4];
    const float* W1 = (const float*)d_in[5];
    const float* b1 = (const float*)d_in[6];
    const float* W2 = (const float*)d_in[7];

    cudaFuncSetAttribute(dyn_kernel, cudaFuncAttributeMaxDynamicSharedMemorySize,
                         (int)SMEM_BYTES);
    dyn_kernel<<<GRID, NTHREADS, SMEM_BYTES>>>(X, Km, Dm, W0, b0, W1, b1, W2,
                                               (float*)d_out);
}

// round 5
// speedup vs baseline: 1.4870x; 1.0606x over previous
#include <cuda_runtime.h>
#include <math.h>

// Dynamics_79843442033036 — fused analytic grad/HVV kernel.
// f32x2 FFMA2, dual-group pipelining, Q-matvec eliminated algebraically,
// all epilogue smem traffic vectorized (float4) to kill 4-way bank conflicts.

typedef unsigned long long ull;

#define HID     128
#define DIMV    8
#define BATCHN  65536
#define TBS     32
#define NTILES  (BATCHN / TBS)      // 2048
#define NTHREADS 512
#define GTHREADS 256
#define GRID    152
#define NWORKERS (GRID * 2)

#define W1P 132
#define XP  17
#define W0P 10
#define HVP 33
#define GBP 9                        // gbf pitch: [s][9]

// ---- shared weights (float offsets) ----
#define SM_W1   0
#define SM_W0   (SM_W1 + HID*W1P)          // 16896
#define SM_W0D  (SM_W0 + HID*W0P)          // 18176
#define SM_B0   (SM_W0D + HID*DIMV*2)      // 20224
#define SM_B1   (SM_B0 + HID)
#define SM_W2   (SM_B1 + HID)
#define SM_K    (SM_W2 + HID)
#define SM_D    (SM_K + 64)
#define SM_GRPBASE (SM_D + 64)             // 20736
// ---- per-group region ----
#define G_H1    0
#define G_E1    (G_H1 + HID*TBS)           // 4096
#define G_F1    (G_E1 + HID*TBS)           // 8192
#define G_X     (G_F1 + HID*TBS)           // 12288  [32][17]
#define G_G     (G_X + TBS*XP)             // 12832  [32][9]
#define G_HVV   (G_G + TBS*GBP)            // 13120  [32]
#define G_HVP   (G_HVV + TBS)              // 13152  [32][33]
#define G_SIZE  (G_HVP + 32*HVP)           // 14208
#define SM_TOTAL (SM_GRPBASE + 2*G_SIZE)
#define SMEM_BYTES (SM_TOTAL * sizeof(float))

__device__ __forceinline__ ull pack2(float x, float y) {
    ull r; asm("mov.b64 %0, {%1,%2};" : "=l"(r) : "f"(x), "f"(y)); return r;
}
__device__ __forceinline__ float2 unpack2(ull v) {
    float2 r; asm("mov.b64 {%0,%1}, %2;" : "=f"(r.x), "=f"(r.y) : "l"(v)); return r;
}
__device__ __forceinline__ ull fma2(ull a, ull b, ull c) {
    ull r; asm("fma.rn.f32x2 %0, %1, %2, %3;" : "=l"(r) : "l"(a), "l"(b), "l"(c)); return r;
}
// fast tanh: 1 - 2/(e^{2z}+1). Correct saturation, rel err ~1e-6.
__device__ __forceinline__ float ftanh(float z) {
    float e = __expf(2.f * z);
    return 1.f - __fdividef(2.f, e + 1.f);
}

extern "C" __global__ void __launch_bounds__(NTHREADS, 1)
dyn_kernel(const float* __restrict__ X,  const float* __restrict__ Km,
           const float* __restrict__ Dm, const float* __restrict__ W0,
           const float* __restrict__ b0, const float* __restrict__ W1,
           const float* __restrict__ b1, const float* __restrict__ W2,
           float* __restrict__ out)
{
    extern __shared__ float sm[];
    float* W1s = sm + SM_W1;
    float* W0s = sm + SM_W0;
    float* W0d = sm + SM_W0D;
    float* b0s = sm + SM_B0;
    float* b1s = sm + SM_B1;
    float* w2s = sm + SM_W2;
    float* Ks  = sm + SM_K;
    float* Ds  = sm + SM_D;

    const int tid   = threadIdx.x;
    const int group = tid >> 8;
    const int gtid  = tid & 255;
    const int gbar  = group + 1;

    float* gbase = sm + SM_GRPBASE + group * G_SIZE;
    float* h1s = gbase + G_H1;
    float* e1s = gbase + G_E1;
    float* f1s = gbase + G_F1;
    float* Xs  = gbase + G_X;
    float* gbf = gbase + G_G;
    float* hvs = gbase + G_HVV;
    float* hvp_s = gbase + G_HVP;

    // ---- one-time weight staging (whole CTA) ----
    for (int idx = tid; idx < HID*HID; idx += NTHREADS) {
        int j = idx >> 7, i = idx & 127;
        W1s[j*W1P + i] = W1[idx];
    }
    for (int idx = tid; idx < HID*DIMV; idx += NTHREADS) {
        int i = idx >> 3, k = idx & 7;
        float w = W0[idx];
        W0s[i*W0P + k] = w;
        W0d[idx*2]     = w;
        W0d[idx*2 + 1] = w;
    }
    if (tid < HID) { b0s[tid] = b0[tid]; b1s[tid] = b1[tid]; w2s[tid] = W2[tid]; }
    if (tid < 64)  { Ks[tid] = Km[tid]; Ds[tid] = Dm[tid]; }
    __syncthreads();

    const int tx = gtid & 7;            // 8 sample-groups x 4 samples
    const int jy = gtid >> 3;           // 32 hidden-groups x 4 rows
    const int s0 = tx * 4;
    const int j0 = jy * 4;
    const int qf = gtid & 7;
    const int sf = gtid >> 3;           // 0..31

    const int worker = blockIdx.x * 2 + group;

    for (int tile = worker; tile < NTILES; tile += NWORKERS) {
        const int base = tile * TBS;

        // ---- stage X tile ----
        for (int idx = gtid; idx < TBS*16; idx += GTHREADS) {
            int s = idx >> 4, k = idx & 15;
            Xs[s*XP + k] = X[base*16 + idx];
        }
        asm volatile("bar.sync %0, 256;" :: "r"(gbar) : "memory");

        // ---- phase 1: h1, h1', h1''  (vectorized stores) ----
        {
            float hh[4][4], ee[4][4], ff[4][4];
            #pragma unroll
            for (int ss = 0; ss < 4; ss++) {
                const int s = s0 + ss;
                float xr[8], vr[8];
                #pragma unroll
                for (int k = 0; k < 8; k++) { xr[k] = Xs[s*XP + k]; vr[k] = Xs[s*XP + 8 + k]; }
                #pragma unroll
                for (int c = 0; c < 4; c++) {
                    const int i = j0 + c;
                    float z = b0s[i], t = 0.f;
                    #pragma unroll
                    for (int k = 0; k < 8; k++) {
                        float w = W0s[i*W0P + k];
                        z = fmaf(w, xr[k], z);
                        t = fmaf(w, vr[k], t);
                    }
                    float h = ftanh(z);
                    float d = 1.f - h*h;
                    float e = d * t;
                    float f = -2.f * h * t * e;
                    hh[c][ss] = h; ee[c][ss] = e; ff[c][ss] = f;
                }
            }
            #pragma unroll
            for (int c = 0; c < 4; c++) {
                const int i = j0 + c;
                *(float4*)(h1s + i*TBS + s0) = make_float4(hh[c][0],hh[c][1],hh[c][2],hh[c][3]);
                *(float4*)(e1s + i*TBS + s0) = make_float4(ee[c][0],ee[c][1],ee[c][2],ee[c][3]);
                *(float4*)(f1s + i*TBS + s0) = make_float4(ff[c][0],ff[c][1],ff[c][2],ff[c][3]);
            }
        }
        asm volatile("bar.sync %0, 256;" :: "r"(gbar) : "memory");

        // ---- phase 2: z2 = W1 h1, P = W1 h1'  (f32x2) ----
        ull az2[4][2], ap2[4][2];
        #pragma unroll
        for (int c = 0; c < 4; c++) {
            az2[c][0]=0ull; az2[c][1]=0ull;
            ap2[c][0]=0ull; ap2[c][1]=0ull;
        }
        {
            const float* hp = h1s + s0;
            const float* ep = e1s + s0;
            #pragma unroll 1
            for (int i = 0; i < HID; i += 4) {
                const float4 wr0 = *(const float4*)(W1s + (j0+0)*W1P + i);
                const float4 wr1 = *(const float4*)(W1s + (j0+1)*W1P + i);
                const float4 wr2 = *(const float4*)(W1s + (j0+2)*W1P + i);
                const float4 wr3 = *(const float4*)(W1s + (j0+3)*W1P + i);
                const float* wa0 = (const float*)&wr0;
                const float* wa1 = (const float*)&wr1;
                const float* wa2 = (const float*)&wr2;
                const float* wa3 = (const float*)&wr3;
                #pragma unroll
                for (int ii = 0; ii < 4; ii++) {
                    const ulonglong2 hv = *(const ulonglong2*)(hp + (i+ii)*TBS);
                    const ulonglong2 ev = *(const ulonglong2*)(ep + (i+ii)*TBS);
                    ull w;
                    w = pack2(wa0[ii], wa0[ii]);
                    az2[0][0]=fma2(w,hv.x,az2[0][0]); az2[0][1]=fma2(w,hv.y,az2[0][1]);
                    ap2[0][0]=fma2(w,ev.x,ap2[0][0]); ap2[0][1]=fma2(w,ev.y,ap2[0][1]);
                    w = pack2(wa1[ii], wa1[ii]);
                    az2[1][0]=fma2(w,hv.x,az2[1][0]); az2[1][1]=fma2(w,hv.y,az2[1][1]);
                    ap2[1][0]=fma2(w,ev.x,ap2[1][0]); ap2[1][1]=fma2(w,ev.y,ap2[1][1]);
                    w = pack2(wa2[ii], wa2[ii]);
                    az2[2][0]=fma2(w,hv.x,az2[2][0]); az2[2][1]=fma2(w,hv.y,az2[2][1]);
                    ap2[2][0]=fma2(w,ev.x,ap2[2][0]); ap2[2][1]=fma2(w,ev.y,ap2[2][1]);
                    w = pack2(wa3[ii], wa3[ii]);
                    az2[3][0]=fma2(w,hv.x,az2[3][0]); az2[3][1]=fma2(w,hv.y,az2[3][1]);
                    ap2[3][0]=fma2(w,ev.x,ap2[3][0]); ap2[3][1]=fma2(w,ev.y,ap2[3][1]);
                }
            }
        }
        asm volatile("bar.sync %0, 256;" :: "r"(gbar) : "memory");  // GEMM reads done

        // ---- phase-2 epilogue: a = d2*w2 -> e1s (float4) ; P-term hvv in regs ----
        float hvp[4] = {0.f, 0.f, 0.f, 0.f};
        {
            #pragma unroll
            for (int c = 0; c < 4; c++) {
                const int j = j0 + c;
                const float2 z01 = unpack2(az2[c][0]), z23 = unpack2(az2[c][1]);
                const float2 p01 = unpack2(ap2[c][0]), p23 = unpack2(ap2[c][1]);
                const float zz[4] = {z01.x, z01.y, z23.x, z23.y};
                const float pp[4] = {p01.x, p01.y, p23.x, p23.y};
                const float w2j = w2s[j];
                const float bj  = b1s[j];
                float av[4];
                #pragma unroll
                for (int ss = 0; ss < 4; ss++) {
                    float h2 = ftanh(zz[ss] + bj);
                    float d2 = 1.f - h2*h2;
                    float P = pp[ss];
                    hvp[ss] = fmaf(-2.f*w2j, h2*d2*P*P, hvp[ss]);
                    av[ss] = d2 * w2j;
                }
                *(float4*)(e1s + j*TBS + s0) = make_float4(av[0],av[1],av[2],av[3]);
            }
        }
        asm volatile("bar.sync %0, 256;" :: "r"(gbar) : "memory");  // a ready

        // ---- phase 3: U = W1^T a (f32x2) ----
        ull au2[4][2];
        #pragma unroll
        for (int c = 0; c < 4; c++) { au2[c][0]=0ull; au2[c][1]=0ull; }
        {
            const float* apnt = e1s + s0;
            #pragma unroll 2
            for (int j = 0; j < HID; j++) {
                const ulonglong2 av = *(const ulonglong2*)(apnt + j*TBS);
                const float4 wv = *(const float4*)(W1s + j*W1P + j0);
                const float* wa = (const float*)&wv;
                ull w;
                w = pack2(wa[0], wa[0]);
                au2[0][0]=fma2(w,av.x,au2[0][0]); au2[0][1]=fma2(w,av.y,au2[0][1]);
                w = pack2(wa[1], wa[1]);
                au2[1][0]=fma2(w,av.x,au2[1][0]); au2[1][1]=fma2(w,av.y,au2[1][1]);
                w = pack2(wa[2], wa[2]);
                au2[2][0]=fma2(w,av.x,au2[2][0]); au2[2][1]=fma2(w,av.y,au2[2][1]);
                w = pack2(wa[3], wa[3]);
                au2[3][0]=fma2(w,av.x,au2[3][0]); au2[3][1]=fma2(w,av.y,au2[3][1]);
            }
        }
        // ---- phase-3 epilogue (vectorized): hvv += U.h1'' ; s = d1*U -> f1s ----
        #pragma unroll
        for (int c = 0; c < 4; c++) {
            const int i = j0 + c;
            const float2 u01 = unpack2(au2[c][0]), u23 = unpack2(au2[c][1]);
            const float uu[4] = {u01.x, u01.y, u23.x, u23.y};
            const float4 fv = *(const float4*)(f1s + i*TBS + s0);
            const float4 hv = *(const float4*)(h1s + i*TBS + s0);
            const float fpp[4] = {fv.x, fv.y, fv.z, fv.w};
            const float hh4[4] = {hv.x, hv.y, hv.z, hv.w};
            float sv[4];
            #pragma unroll
            for (int ss = 0; ss < 4; ss++) {
                hvp[ss] = fmaf(uu[ss], fpp[ss], hvp[ss]);
                sv[ss]  = (1.f - hh4[ss]*hh4[ss]) * uu[ss];
            }
            *(float4*)(f1s + i*TBS + s0) = make_float4(sv[0],sv[1],sv[2],sv[3]);
        }
        #pragma unroll
        for (int ss = 0; ss < 4; ss++)
            hvp_s[jy*HVP + s0 + ss] = hvp[ss];
        asm volatile("bar.sync %0, 256;" :: "r"(gbar) : "memory");

        // ---- phase 4 (warps 0-3): g = W0^T s  ||  hvv reduce (warp 4) ----
        if (gtid < 128) {
            const int q  = gtid & 7;
            const int sp = gtid >> 3;        // sample pair 0..15
            ull acc = 0ull;
            const ull* w0dp = (const ull*)(W0d) + q;
            const float* fp = f1s + 2*sp;
            #pragma unroll 4
            for (int i = 0; i < HID; i++)
                acc = fma2(w0dp[i*8], *(const ull*)(fp + i*TBS), acc);
            float2 gv = unpack2(acc);
            gbf[(2*sp)*GBP + q]     = gv.x;
            gbf[(2*sp+1)*GBP + q]   = gv.y;
        } else if (gtid < 160) {
            const int s = gtid - 128;
            float acc = 0.f;
            #pragma unroll
            for (int g = 0; g < 32; g++) acc += hvp_s[g*HVP + s];
            hvs[s] = acc;
        }
        asm volatile("bar.sync %0, 256;" :: "r"(gbar) : "memory");

        // ---- phase 5: Sherman-Morrison combine + coalesced store ----
        {
            float g[8];
            #pragma unroll
            for (int k = 0; k < 8; k++) g[k] = gbf[sf*GBP + k];
            float gg = 0.f;
            #pragma unroll
            for (int k = 0; k < 8; k++) gg = fmaf(g[k], g[k], gg);
            float xr[8], vr[8];
            #pragma unroll
            for (int k = 0; k < 8; k++) { xr[k] = Xs[sf*XP + k]; vr[k] = Xs[sf*XP + 8 + k]; }
            float gf = 0.f, fq = 0.f;
            #pragma unroll
            for (int q2 = 0; q2 < 8; q2++) {
                float fo = 0.f;
                #pragma unroll
                for (int k = 0; k < 8; k++) {
                    fo = fmaf(-Ds[q2*8+k], vr[k], fo);
                    fo = fmaf(-Ks[q2*8+k], xr[k], fo);
                }
                gf = fmaf(g[q2], fo, gf);
                if (q2 == qf) fq = fo;
            }
            float scale = (gf + hvs[sf]) / (1.f + gg);
            out[(base + sf)*8 + qf] = fq - g[qf]*scale;
        }
        asm volatile("bar.sync %0, 256;" :: "r"(gbar) : "memory");
    }
}

extern "C" void kernel_launch(void* const* d_in, const int* in_sizes, int n_in,
                              void* d_out, int out_size)
{
    const float* X  = (const float*)d_in[0];
    const float* Km = (const float*)d_in[1];
    const float* Dm = (const float*)d_in[2];
    const float* W0 = (const float*)d_in[3];
    const float* b0 = (const float*)d_in[4];
    const float* W1 = (const float*)d_in[5];
    const float* b1 = (const float*)d_in[6];
    const float* W2 = (const float*)d_in[7];

    cudaFuncSetAttribute(dyn_kernel, cudaFuncAttributeMaxDynamicSharedMemorySize,
                         (int)SMEM_BYTES);
    dyn_kernel<<<GRID, NTHREADS, SMEM_BYTES>>>(X, Km, Dm, W0, b0, W1, b1, W2,
                                               (float*)d_out);
}